// round 12
// baseline (speedup 1.0000x reference)
#include <cuda_runtime.h>
#include <cuda_fp16.h>
#include <cstdint>

// ---------------------------------------------------------------------------
// Ragged batched QK^T (static): B=32, H=16, E=64, SEQLEN[i]=256+(37i)%257,
// out = concat_b [H, L_b, L_b], scale = 0.125.
// fp16 inputs (rn) + f32 acc, m16n8k16 mma.sync, one 128x128 tile per CTA,
// single-pass width-2 staged epilogue (stride-72, conflict-free).
// This round: 32-bit indexing everywhere + __launch_bounds__(256,3)
// -> 84-reg build, 3 CTAs/SM (24 warps) with identical L1 work.
// ---------------------------------------------------------------------------
#define NB 32
#define NH 16
#define NE 64
#define BM 128
#define BN 128
#define TPAD 144                    // bytes per fp16 smem tile row (128+16 pad)
#define TILEB (BM * TPAD)           // 18432 B
#define SSTR 72                     // staging stride (floats)
#define SWARP (32 * SSTR)           // staging floats per warp (2304)

struct Tables {
    int seqlen[NB];
    int tok_base[NB];
    unsigned out_base[NB];          // fits: total out = 70.6M elements
    int blk_base[NB + 1];
};

constexpr Tables make_tables() {
    Tables t{};
    int tb = 0; unsigned long long ob = 0; int bb = 0;
    for (int i = 0; i < NB; i++) {
        int L = 256 + (i * 37) % 257;
        t.seqlen[i] = L; t.tok_base[i] = tb;
        t.out_base[i] = (unsigned)ob; t.blk_base[i] = bb;
        int nt = (L + BM - 1) / BM;
        tb += L; ob += (unsigned long long)NH * L * L; bb += NH * nt * nt;
    }
    t.blk_base[NB] = bb;
    return t;
}

__constant__ Tables dtab = make_tables();

__device__ __forceinline__ uint32_t cvta_sm(const void* p) {
    uint32_t a;
    asm("{ .reg .u64 t; cvta.to.shared.u64 t, %1; cvt.u32.u64 %0, t; }"
        : "=r"(a) : "l"(p));
    return a;
}

__device__ __forceinline__ void ldm4(uint32_t* r, uint32_t addr) {
    asm volatile(
        "ldmatrix.sync.aligned.m8n8.x4.shared.b16 {%0,%1,%2,%3}, [%4];"
        : "=r"(r[0]), "=r"(r[1]), "=r"(r[2]), "=r"(r[3]) : "r"(addr));
}

__device__ __forceinline__ void mma_f16(float* d, const uint32_t* a,
                                        uint32_t b0, uint32_t b1) {
    asm volatile(
        "mma.sync.aligned.m16n8k16.row.col.f32.f16.f16.f32 "
        "{%0,%1,%2,%3}, {%4,%5,%6,%7}, {%8,%9}, {%0,%1,%2,%3};"
        : "+f"(d[0]), "+f"(d[1]), "+f"(d[2]), "+f"(d[3])
        : "r"(a[0]), "r"(a[1]), "r"(a[2]), "r"(a[3]), "r"(b0), "r"(b1));
}

__global__ __launch_bounds__(256, 3) void bmm1_fp16(
    const float* __restrict__ Q,
    const float* __restrict__ K,
    float* __restrict__ out)
{
    extern __shared__ __align__(16) char sm[];
    char* smQ = sm;                           // fp16 [128][TPAD]
    char* smK = sm + TILEB;

    const int bid = blockIdx.x;

    // ---- locate (batch, head, qtile, ktile) ----
    int b = 0;
#pragma unroll
    for (int i = 1; i < NB; i++) b += (bid >= dtab.blk_base[i]);
    const int L  = dtab.seqlen[b];
    const int nt = (L + 127) >> 7;
    int rem = bid - dtab.blk_base[b];
    const int h  = rem / (nt * nt);
    rem -= h * (nt * nt);
    const int qt = rem / nt;
    const int kt = rem - qt * nt;

    const int tid = threadIdx.x;
    // 32-bit input indexing: max token offset 11638*1024 < 2^31
    const int rowstride = NH * NE;            // 1024 floats/token
    const float* qbase = Q + dtab.tok_base[b] * rowstride + h * NE;
    const float* kbase = K + dtab.tok_base[b] * rowstride + h * NE;

    // ---- global f32 -> smem fp16 tiles (inline rn convert, zero-fill) ----
    {
        const int c4 = tid & 15;
        const int rl = tid >> 4;
#pragma unroll
        for (int g = 0; g < 8; g++) {
            const int m = rl + g * 16;

            const int qrow = qt * BM + m;
            float4 v = (qrow < L)
                ? *(const float4*)(qbase + qrow * rowstride + c4 * 4)
                : make_float4(0.f, 0.f, 0.f, 0.f);
            __half2 h0 = __floats2half2_rn(v.x, v.y);
            __half2 h1 = __floats2half2_rn(v.z, v.w);
            *(uint2*)(smQ + m * TPAD + c4 * 8) =
                make_uint2(*(uint32_t*)&h0, *(uint32_t*)&h1);

            const int krow = kt * BN + m;
            float4 u = (krow < L)
                ? *(const float4*)(kbase + krow * rowstride + c4 * 4)
                : make_float4(0.f, 0.f, 0.f, 0.f);
            h0 = __floats2half2_rn(u.x, u.y);
            h1 = __floats2half2_rn(u.z, u.w);
            *(uint2*)(smK + m * TPAD + c4 * 8) =
                make_uint2(*(uint32_t*)&h0, *(uint32_t*)&h1);
        }
    }
    __syncthreads();

    // ---- warp layout: 8 warps = 4(m) x 2(n); warp tile 32m x 64n ----
    const int wid = tid >> 5, l = tid & 31;
    const int wm = wid & 3, wn = wid >> 2;

    const uint32_t smbase = cvta_sm(sm);
    const uint32_t a_off = smbase
        + (wm * 32 + (l & 7) + ((l >> 3) & 1) * 8) * TPAD
        + ((l >> 4) & 1) * 16;
    const uint32_t b_base = smbase + TILEB
        + (wn * 64 + (l & 7) + ((l >> 4) & 1) * 8) * TPAD
        + ((l >> 3) & 1) * 16;

    float acc[2][8][4];
#pragma unroll
    for (int mi = 0; mi < 2; mi++)
#pragma unroll
        for (int ni = 0; ni < 8; ni++)
#pragma unroll
            for (int r = 0; r < 4; r++) acc[mi][ni][r] = 0.f;

#pragma unroll
    for (int ks = 0; ks < 4; ks++) {          // 4 k-steps of 16
        const uint32_t koff = ks * 32;        // 16 halves = 32B
        uint32_t A0[4], A1[4];
        ldm4(A0, a_off + koff);
        ldm4(A1, a_off + 16 * TPAD + koff);
#pragma unroll
        for (int j = 0; j < 4; j++) {         // JIT B fragments
            uint32_t Bf[4];
            ldm4(Bf, b_base + j * (16 * TPAD) + koff);
#pragma unroll
            for (int p = 0; p < 2; p++) {
                const int ni = j * 2 + p;
                mma_f16(acc[0][ni], A0, Bf[p * 2], Bf[p * 2 + 1]);
                mma_f16(acc[1][ni], A1, Bf[p * 2], Bf[p * 2 + 1]);
            }
        }
    }

    // ---- single-pass staged epilogue (staging overlays tile smem) ----
    __syncthreads();   // all warps finished reading tiles
    float* wst = (float*)sm + wid * SWARP;    // [32 rows][SSTR floats]
    const float sc = 0.125f;

#pragma unroll
    for (int mi = 0; mi < 2; mi++)
#pragma unroll
        for (int h2 = 0; h2 < 2; h2++) {
            const int r = mi * 16 + h2 * 8 + (l >> 2);
#pragma unroll
            for (int ni = 0; ni < 8; ni++) {
                *(float2*)&wst[r * SSTR + ni * 8 + 2 * (l & 3)] =
                    make_float2(acc[mi][ni][h2 * 2 + 0] * sc,
                                acc[mi][ni][h2 * 2 + 1] * sc);
            }
        }
    __syncwarp();

    // store: lane l covers column pair n0w + {2l, 2l+1}, all rows; 32-bit idx
    const int q0w = qt * BM + wm * 32;
    const int n0w = kt * BN + wn * 64;
    const unsigned obase = dtab.out_base[b] + (unsigned)h * (unsigned)(L * L);
    const int rmax = min(32, L - q0w);
    const int n = n0w + 2 * l;
    const float* src = wst + 2 * l;
    float* dst = out + obase + (unsigned)q0w * (unsigned)L + n;

    if (!(L & 1)) {
        // even L: obase, q*L, n all even -> 8B-aligned; n<L implies n+1<L
        if (n < L) {
#pragma unroll 8
            for (int r = 0; r < rmax; r++) {
                const float2 v = *(const float2*)(src + r * SSTR);
                __stcs((float2*)(dst + r * L), v);
            }
        }
    } else {
        const bool v0 = n < L, v1 = n + 1 < L;
#pragma unroll 8
        for (int r = 0; r < rmax; r++) {
            const float2 v = *(const float2*)(src + r * SSTR);
            float* p = dst + r * L;
            if (v0) __stcs(p, v.x);
            if (v1) __stcs(p + 1, v.y);
        }
    }
}

extern "C" void kernel_launch(void* const* d_in, const int* in_sizes, int n_in,
                              void* d_out, int out_size)
{
    const float* q = (const float*)d_in[0];
    const float* k = (const float*)d_in[1];
    float* o = (float*)d_out;

    constexpr Tables ht = make_tables();
    const int nblocks = ht.blk_base[NB];     // 5872

    constexpr int smem = 8 * SWARP * (int)sizeof(float);   // 73728
    cudaFuncSetAttribute(bmm1_fp16,
                         cudaFuncAttributeMaxDynamicSharedMemorySize, smem);
    bmm1_fp16<<<nblocks, 256, smem>>>(q, k, o);
}

// round 13
// speedup vs baseline: 1.2040x; 1.2040x over previous
#include <cuda_runtime.h>
#include <cuda_fp16.h>
#include <cstdint>

// ---------------------------------------------------------------------------
// Ragged batched QK^T (static): B=32, H=16, E=64, SEQLEN[i]=256+(37i)%257,
// out = concat_b [H, L_b, L_b], scale = 0.125 (folded into Q at load).
// fp16 inputs + f32 acc m16n8k16 mma.sync, one 128x128 tile per CTA.
// Epilogue: f16 staging via stmatrix.x4 (half the staging L1 bytes),
// LDS.32 half2 readback -> cvt -> coalesced STG.64 streaming stores.
// Staging in dedicated smem: no block-wide sync before epilogue.
// ---------------------------------------------------------------------------
#define NB 32
#define NH 16
#define NE 64
#define BM 128
#define BN 128
#define TPAD 144                    // bytes per fp16 smem tile row (128+16 pad)
#define TILEB (BM * TPAD)           // 18432 B
#define SSTRB 144                   // staging row stride BYTES (128 data + 16)
#define SWARPB (32 * SSTRB)         // staging bytes per warp (4608)

struct Tables {
    int seqlen[NB];
    int tok_base[NB];
    unsigned out_base[NB];          // total out = 70.6M elements < 2^31
    int blk_base[NB + 1];
};

constexpr Tables make_tables() {
    Tables t{};
    int tb = 0; unsigned long long ob = 0; int bb = 0;
    for (int i = 0; i < NB; i++) {
        int L = 256 + (i * 37) % 257;
        t.seqlen[i] = L; t.tok_base[i] = tb;
        t.out_base[i] = (unsigned)ob; t.blk_base[i] = bb;
        int nt = (L + BM - 1) / BM;
        tb += L; ob += (unsigned long long)NH * L * L; bb += NH * nt * nt;
    }
    t.blk_base[NB] = bb;
    return t;
}

__constant__ Tables dtab = make_tables();

__device__ __forceinline__ uint32_t cvta_sm(const void* p) {
    uint32_t a;
    asm("{ .reg .u64 t; cvta.to.shared.u64 t, %1; cvt.u32.u64 %0, t; }"
        : "=r"(a) : "l"(p));
    return a;
}

__device__ __forceinline__ void ldm4(uint32_t* r, uint32_t addr) {
    asm volatile(
        "ldmatrix.sync.aligned.m8n8.x4.shared.b16 {%0,%1,%2,%3}, [%4];"
        : "=r"(r[0]), "=r"(r[1]), "=r"(r[2]), "=r"(r[3]) : "r"(addr));
}

__device__ __forceinline__ void stsm4(uint32_t addr, uint32_t r0, uint32_t r1,
                                      uint32_t r2, uint32_t r3) {
    asm volatile(
        "stmatrix.sync.aligned.m8n8.x4.shared.b16 [%0], {%1,%2,%3,%4};"
        :: "r"(addr), "r"(r0), "r"(r1), "r"(r2), "r"(r3) : "memory");
}

__device__ __forceinline__ void mma_f16(float* d, const uint32_t* a,
                                        uint32_t b0, uint32_t b1) {
    asm volatile(
        "mma.sync.aligned.m16n8k16.row.col.f32.f16.f16.f32 "
        "{%0,%1,%2,%3}, {%4,%5,%6,%7}, {%8,%9}, {%0,%1,%2,%3};"
        : "+f"(d[0]), "+f"(d[1]), "+f"(d[2]), "+f"(d[3])
        : "r"(a[0]), "r"(a[1]), "r"(a[2]), "r"(a[3]), "r"(b0), "r"(b1));
}

__global__ __launch_bounds__(256, 2) void bmm1_fp16(
    const float* __restrict__ Q,
    const float* __restrict__ K,
    float* __restrict__ out)
{
    extern __shared__ __align__(16) char sm[];
    char* smQ = sm;                           // fp16 [128][TPAD]
    char* smK = sm + TILEB;
    char* smS = sm + 2 * TILEB;               // staging: 8 warps x SWARPB

    const int bid = blockIdx.x;

    // ---- locate (batch, head, qtile, ktile) ----
    int b = 0;
#pragma unroll
    for (int i = 1; i < NB; i++) b += (bid >= dtab.blk_base[i]);
    const int L  = dtab.seqlen[b];
    const int nt = (L + 127) >> 7;
    int rem = bid - dtab.blk_base[b];
    const int h  = rem / (nt * nt);
    rem -= h * (nt * nt);
    const int qt = rem / nt;
    const int kt = rem - qt * nt;

    const int tid = threadIdx.x;
    const int rowstride = NH * NE;            // 1024 floats/token (32-bit idx)
    const float* qbase = Q + dtab.tok_base[b] * rowstride + h * NE;
    const float* kbase = K + dtab.tok_base[b] * rowstride + h * NE;

    // ---- global f32 -> smem fp16 tiles; Q pre-scaled by 0.125 (exact) ----
    {
        const int c4 = tid & 15;
        const int rl = tid >> 4;
#pragma unroll
        for (int g = 0; g < 8; g++) {
            const int m = rl + g * 16;

            const int qrow = qt * BM + m;
            float4 v = (qrow < L)
                ? *(const float4*)(qbase + qrow * rowstride + c4 * 4)
                : make_float4(0.f, 0.f, 0.f, 0.f);
            __half2 h0 = __floats2half2_rn(v.x * 0.125f, v.y * 0.125f);
            __half2 h1 = __floats2half2_rn(v.z * 0.125f, v.w * 0.125f);
            *(uint2*)(smQ + m * TPAD + c4 * 8) =
                make_uint2(*(uint32_t*)&h0, *(uint32_t*)&h1);

            const int krow = kt * BN + m;
            float4 u = (krow < L)
                ? *(const float4*)(kbase + krow * rowstride + c4 * 4)
                : make_float4(0.f, 0.f, 0.f, 0.f);
            h0 = __floats2half2_rn(u.x, u.y);
            h1 = __floats2half2_rn(u.z, u.w);
            *(uint2*)(smK + m * TPAD + c4 * 8) =
                make_uint2(*(uint32_t*)&h0, *(uint32_t*)&h1);
        }
    }
    __syncthreads();

    // ---- warp layout: 8 warps = 4(m) x 2(n); warp tile 32m x 64n ----
    const int wid = tid >> 5, l = tid & 31;
    const int wm = wid & 3, wn = wid >> 2;

    const uint32_t smbase = cvta_sm(sm);
    const uint32_t a_off = smbase
        + (wm * 32 + (l & 7) + ((l >> 3) & 1) * 8) * TPAD
        + ((l >> 4) & 1) * 16;
    const uint32_t b_base = smbase + TILEB
        + (wn * 64 + (l & 7) + ((l >> 4) & 1) * 8) * TPAD
        + ((l >> 3) & 1) * 16;

    float acc[2][8][4];
#pragma unroll
    for (int mi = 0; mi < 2; mi++)
#pragma unroll
        for (int ni = 0; ni < 8; ni++)
#pragma unroll
            for (int r = 0; r < 4; r++) acc[mi][ni][r] = 0.f;

#pragma unroll
    for (int ks = 0; ks < 4; ks++) {          // 4 k-steps of 16
        const uint32_t koff = ks * 32;        // 16 halves = 32B
        uint32_t A0[4], A1[4];
        ldm4(A0, a_off + koff);
        ldm4(A1, a_off + 16 * TPAD + koff);
#pragma unroll
        for (int j = 0; j < 4; j++) {         // JIT B fragments
            uint32_t Bf[4];
            ldm4(Bf, b_base + j * (16 * TPAD) + koff);
#pragma unroll
            for (int p = 0; p < 2; p++) {
                const int ni = j * 2 + p;
                mma_f16(acc[0][ni], A0, Bf[p * 2], Bf[p * 2 + 1]);
                mma_f16(acc[1][ni], A1, Bf[p * 2], Bf[p * 2 + 1]);
            }
        }
    }

    // ---- epilogue: f16 staging via stmatrix (no block-wide sync) ----
    // staging layout per warp: [32 rows][SSTRB bytes], row = m within 32,
    // halves 0..63 = cols. stmatrix call g stores col-block g (8 cols),
    // 4 row-blocks; lane i addresses row i, byte offset g*16.
    const uint32_t stw = cvta_sm(smS) + wid * SWARPB;
    const uint32_t staddr = stw + (uint32_t)l * SSTRB;

#pragma unroll
    for (int g = 0; g < 8; g++) {
        __half2 p0 = __floats2half2_rn(acc[0][g][0], acc[0][g][1]);
        __half2 p1 = __floats2half2_rn(acc[0][g][2], acc[0][g][3]);
        __half2 p2 = __floats2half2_rn(acc[1][g][0], acc[1][g][1]);
        __half2 p3 = __floats2half2_rn(acc[1][g][2], acc[1][g][3]);
        stsm4(staddr + g * 16,
              *(uint32_t*)&p0, *(uint32_t*)&p1,
              *(uint32_t*)&p2, *(uint32_t*)&p3);
    }
    __syncwarp();

    // store pass: lane l covers column pair n0w + {2l, 2l+1}, all 32 rows.
    const int q0w = qt * BM + wm * 32;
    const int n0w = kt * BN + wn * 64;
    const unsigned obase = dtab.out_base[b] + (unsigned)h * (unsigned)(L * L);
    const int rmax = min(32, L - q0w);
    const int n = n0w + 2 * l;
    const uint32_t src = stw + (uint32_t)l * 4;
    float* dst = out + obase + (unsigned)q0w * (unsigned)L + n;

    if (!(L & 1)) {
        // even L: obase, q*L, n all even -> 8B-aligned; n<L implies n+1<L
        if (n < L) {
#pragma unroll 8
            for (int r = 0; r < rmax; r++) {
                uint32_t hv;
                asm volatile("ld.shared.b32 %0, [%1];"
                             : "=r"(hv) : "r"(src + r * SSTRB));
                const float2 v = __half22float2(*(const __half2*)&hv);
                __stcs((float2*)(dst + r * L), v);
            }
        }
    } else {
        const bool v0 = n < L, v1 = n + 1 < L;
#pragma unroll 8
        for (int r = 0; r < rmax; r++) {
            uint32_t hv;
            asm volatile("ld.shared.b32 %0, [%1];"
                         : "=r"(hv) : "r"(src + r * SSTRB));
            const float2 v = __half22float2(*(const __half2*)&hv);
            float* p = dst + r * L;
            if (v0) __stcs(p, v.x);
            if (v1) __stcs(p + 1, v.y);
        }
    }
}

extern "C" void kernel_launch(void* const* d_in, const int* in_sizes, int n_in,
                              void* d_out, int out_size)
{
    const float* q = (const float*)d_in[0];
    const float* k = (const float*)d_in[1];
    float* o = (float*)d_out;

    constexpr Tables ht = make_tables();
    const int nblocks = ht.blk_base[NB];     // 5872

    constexpr int smem = 2 * TILEB + 8 * SWARPB;   // 73728 B
    cudaFuncSetAttribute(bmm1_fp16,
                         cudaFuncAttributeMaxDynamicSharedMemorySize, smem);
    bmm1_fp16<<<nblocks, 256, smem>>>(q, k, o);
}

// round 14
// speedup vs baseline: 1.4234x; 1.1822x over previous
#include <cuda_runtime.h>
#include <cuda_fp16.h>
#include <cstdint>

// ---------------------------------------------------------------------------
// Ragged batched QK^T (static): B=32, H=16, E=64, SEQLEN[i]=256+(37i)%257,
// out = concat_b [H, L_b, L_b], scale = 0.125.
// fp16 inputs (rn) + f32 acc, m16n8k16 mma.sync.
// This round: 128-thread CTAs, 64x128 tile (2m x 2n warps, warp tile 32x64
// identical to R11), 4 independent CTAs/SM under the 64K RF.
// Single-pass width-2 staged f32 epilogue (stride-72), staging overlaid.
// ---------------------------------------------------------------------------
#define NB 32
#define NH 16
#define NE 64
#define BM 64                       // CTA tile rows (Q)
#define BN 128                      // CTA tile cols (K rows)
#define TPAD 144                    // bytes per fp16 smem tile row (128+16 pad)
#define QTILEB (BM * TPAD)          // 9216 B
#define KTILEB (BN * TPAD)          // 18432 B
#define SSTR 72                     // staging stride (floats)
#define SWARP (32 * SSTR)           // staging floats per warp (2304)

struct Tables {
    int seqlen[NB];
    int tok_base[NB];
    unsigned out_base[NB];          // total out = 70.6M elements < 2^31
    int blk_base[NB + 1];           // prefix of NH * ntm * ntn
};

constexpr Tables make_tables() {
    Tables t{};
    int tb = 0; unsigned long long ob = 0; int bb = 0;
    for (int i = 0; i < NB; i++) {
        int L = 256 + (i * 37) % 257;
        t.seqlen[i] = L; t.tok_base[i] = tb;
        t.out_base[i] = (unsigned)ob; t.blk_base[i] = bb;
        int ntm = (L + BM - 1) / BM;
        int ntn = (L + BN - 1) / BN;
        tb += L; ob += (unsigned long long)NH * L * L; bb += NH * ntm * ntn;
    }
    t.blk_base[NB] = bb;
    return t;
}

__constant__ Tables dtab = make_tables();

__device__ __forceinline__ uint32_t cvta_sm(const void* p) {
    uint32_t a;
    asm("{ .reg .u64 t; cvta.to.shared.u64 t, %1; cvt.u32.u64 %0, t; }"
        : "=r"(a) : "l"(p));
    return a;
}

__device__ __forceinline__ void ldm4(uint32_t* r, uint32_t addr) {
    asm volatile(
        "ldmatrix.sync.aligned.m8n8.x4.shared.b16 {%0,%1,%2,%3}, [%4];"
        : "=r"(r[0]), "=r"(r[1]), "=r"(r[2]), "=r"(r[3]) : "r"(addr));
}

__device__ __forceinline__ void mma_f16(float* d, const uint32_t* a,
                                        uint32_t b0, uint32_t b1) {
    asm volatile(
        "mma.sync.aligned.m16n8k16.row.col.f32.f16.f16.f32 "
        "{%0,%1,%2,%3}, {%4,%5,%6,%7}, {%8,%9}, {%0,%1,%2,%3};"
        : "+f"(d[0]), "+f"(d[1]), "+f"(d[2]), "+f"(d[3])
        : "r"(a[0]), "r"(a[1]), "r"(a[2]), "r"(a[3]), "r"(b0), "r"(b1));
}

__global__ __launch_bounds__(128, 4) void bmm1_fp16(
    const float* __restrict__ Q,
    const float* __restrict__ K,
    float* __restrict__ out)
{
    extern __shared__ __align__(16) char sm[];
    char* smQ = sm;                           // fp16 [64][TPAD]
    char* smK = sm + QTILEB;                  // fp16 [128][TPAD]

    const int bid = blockIdx.x;

    // ---- locate (batch, head, qtile, ktile) ----
    int b = 0;
#pragma unroll
    for (int i = 1; i < NB; i++) b += (bid >= dtab.blk_base[i]);
    const int L   = dtab.seqlen[b];
    const int ntm = (L + BM - 1) / BM;
    const int ntn = (L + BN - 1) / BN;
    int rem = bid - dtab.blk_base[b];
    const int h  = rem / (ntm * ntn);
    rem -= h * (ntm * ntn);
    const int qt = rem / ntn;
    const int kt = rem - qt * ntn;

    const int tid = threadIdx.x;
    const int rowstride = NH * NE;            // 1024 floats/token (32-bit idx)
    const float* qbase = Q + dtab.tok_base[b] * rowstride + h * NE;
    const float* kbase = K + dtab.tok_base[b] * rowstride + h * NE;

    // ---- global f32 -> smem fp16 tiles (inline rn convert, zero-fill) ----
    {
        const int c4 = tid & 15;              // float4 column within row
        const int rl = tid >> 4;              // 8 rows per pass

        // Q: 64 rows -> 8 passes
#pragma unroll
        for (int g = 0; g < 8; g++) {
            const int m = rl + g * 8;
            const int qrow = qt * BM + m;
            float4 v = (qrow < L)
                ? *(const float4*)(qbase + qrow * rowstride + c4 * 4)
                : make_float4(0.f, 0.f, 0.f, 0.f);
            __half2 h0 = __floats2half2_rn(v.x, v.y);
            __half2 h1 = __floats2half2_rn(v.z, v.w);
            *(uint2*)(smQ + m * TPAD + c4 * 8) =
                make_uint2(*(uint32_t*)&h0, *(uint32_t*)&h1);
        }
        // K: 128 rows -> 16 passes
#pragma unroll
        for (int g = 0; g < 16; g++) {
            const int m = rl + g * 8;
            const int krow = kt * BN + m;
            float4 u = (krow < L)
                ? *(const float4*)(kbase + krow * rowstride + c4 * 4)
                : make_float4(0.f, 0.f, 0.f, 0.f);
            __half2 h0 = __floats2half2_rn(u.x, u.y);
            __half2 h1 = __floats2half2_rn(u.z, u.w);
            *(uint2*)(smK + m * TPAD + c4 * 8) =
                make_uint2(*(uint32_t*)&h0, *(uint32_t*)&h1);
        }
    }
    __syncthreads();

    // ---- warp layout: 4 warps = 2(m) x 2(n); warp tile 32m x 64n ----
    const int wid = tid >> 5, l = tid & 31;
    const int wm = wid & 1, wn = wid >> 1;

    const uint32_t smbase = cvta_sm(sm);
    const uint32_t a_off = smbase
        + (wm * 32 + (l & 7) + ((l >> 3) & 1) * 8) * TPAD
        + ((l >> 4) & 1) * 16;
    const uint32_t b_base = smbase + QTILEB
        + (wn * 64 + (l & 7) + ((l >> 4) & 1) * 8) * TPAD
        + ((l >> 3) & 1) * 16;

    float acc[2][8][4];
#pragma unroll
    for (int mi = 0; mi < 2; mi++)
#pragma unroll
        for (int ni = 0; ni < 8; ni++)
#pragma unroll
            for (int r = 0; r < 4; r++) acc[mi][ni][r] = 0.f;

#pragma unroll
    for (int ks = 0; ks < 4; ks++) {          // 4 k-steps of 16
        const uint32_t koff = ks * 32;        // 16 halves = 32B
        uint32_t A0[4], A1[4];
        ldm4(A0, a_off + koff);
        ldm4(A1, a_off + 16 * TPAD + koff);
#pragma unroll
        for (int j = 0; j < 4; j++) {         // JIT B fragments
            uint32_t Bf[4];
            ldm4(Bf, b_base + j * (16 * TPAD) + koff);
#pragma unroll
            for (int p = 0; p < 2; p++) {
                const int ni = j * 2 + p;
                mma_f16(acc[0][ni], A0, Bf[p * 2], Bf[p * 2 + 1]);
                mma_f16(acc[1][ni], A1, Bf[p * 2], Bf[p * 2 + 1]);
            }
        }
    }

    // ---- single-pass staged epilogue (staging overlays tile smem) ----
    __syncthreads();   // all warps finished reading tiles
    float* wst = (float*)sm + wid * SWARP;    // [32 rows][SSTR floats]
    const float sc = 0.125f;

#pragma unroll
    for (int mi = 0; mi < 2; mi++)
#pragma unroll
        for (int h2 = 0; h2 < 2; h2++) {
            const int r = mi * 16 + h2 * 8 + (l >> 2);
#pragma unroll
            for (int ni = 0; ni < 8; ni++) {
                *(float2*)&wst[r * SSTR + ni * 8 + 2 * (l & 3)] =
                    make_float2(acc[mi][ni][h2 * 2 + 0] * sc,
                                acc[mi][ni][h2 * 2 + 1] * sc);
            }
        }
    __syncwarp();

    // store: lane l covers column pair n0w + {2l, 2l+1}, all 32 rows
    const int q0w = qt * BM + wm * 32;
    const int n0w = kt * BN + wn * 64;
    const unsigned obase = dtab.out_base[b] + (unsigned)h * (unsigned)(L * L);
    const int rmax = min(32, L - q0w);
    const int n = n0w + 2 * l;
    const float* src = wst + 2 * l;
    float* dst = out + obase + (unsigned)q0w * (unsigned)L + n;

    if (!(L & 1)) {
        // even L: obase, q*L, n all even -> 8B-aligned; n<L implies n+1<L
        if (n < L) {
#pragma unroll 8
            for (int r = 0; r < rmax; r++) {
                const float2 v = *(const float2*)(src + r * SSTR);
                __stcs((float2*)(dst + r * L), v);
            }
        }
    } else {
        const bool v0 = n < L, v1 = n + 1 < L;
#pragma unroll 8
        for (int r = 0; r < rmax; r++) {
            const float2 v = *(const float2*)(src + r * SSTR);
            float* p = dst + r * L;
            if (v0) __stcs(p, v.x);
            if (v1) __stcs(p + 1, v.y);
        }
    }
}

extern "C" void kernel_launch(void* const* d_in, const int* in_sizes, int n_in,
                              void* d_out, int out_size)
{
    const float* q = (const float*)d_in[0];
    const float* k = (const float*)d_in[1];
    float* o = (float*)d_out;

    constexpr Tables ht = make_tables();
    const int nblocks = ht.blk_base[NB];

    // staging (4 * SWARP * 4 = 36864 B) overlays tiles (27648 B)
    constexpr int smem = 4 * SWARP * (int)sizeof(float);   // 36864
    cudaFuncSetAttribute(bmm1_fp16,
                         cudaFuncAttributeMaxDynamicSharedMemorySize, smem);
    bmm1_fp16<<<nblocks, 128, smem>>>(q, k, o);
}